// round 5
// baseline (speedup 1.0000x reference)
#include <cuda_runtime.h>
#include <cstdint>

// CorrelationLayer1D: out[b,d,h,w] = sum_c x1[b,c,h,w]*x2pad[b,c,h,w+d]
// B=8,C=256,H=96,W=320,D=41. R5: swizzle-invariant strides (WB=384) ->
// zero per-cc address ALU; 1 sync/chunk; union even-pairs (fixed compile).

#define Cc 256
#define Hh 96
#define Ww 320
#define Dd 41
#define KC 16
#define NCH (Cc / KC)
#define CHW (Hh * Ww)
#define WB 384
#define SA_CHR 80
#define SB_CHR 96
#define SA_BY (KC * Ww * 4)     // 20480
#define SB_BY (KC * WB * 4)     // 24576
#define BUF_BY (SA_BY + SB_BY)  // 45056

typedef unsigned long long ull;

static __device__ __forceinline__ ull pk2(float x, float y) {
    ull r; asm("mov.b64 %0, {%1,%2};" : "=l"(r) : "f"(x), "f"(y)); return r;
}
static __device__ __forceinline__ void upk2(ull v, float& x, float& y) {
    asm("mov.b64 {%0,%1}, %2;" : "=f"(x), "=f"(y) : "l"(v));
}
static __device__ __forceinline__ void ffma2(ull& d, ull a, ull b) {
    asm("fma.rn.f32x2 %0, %1, %2, %0;" : "+l"(d) : "l"(a), "l"(b));
}
static __device__ __forceinline__ int swzq(int q) { return q ^ ((q >> 3) & 1); }
static __device__ __forceinline__ void cp16(uint32_t s, const void* g) {
    asm volatile("cp.async.cg.shared.global [%0], [%1], 16;" :: "r"(s), "l"(g));
}
static __device__ __forceinline__ void cp_commit() {
    asm volatile("cp.async.commit_group;");
}
static __device__ __forceinline__ void cp_wait0() {
    asm volatile("cp.async.wait_group 0;");
}

union LQ { float4 f; ulonglong2 u; };

__global__ __launch_bounds__(256, 2)
void corr1d_kernel(const float* __restrict__ x1, const float* __restrict__ x2,
                   float* __restrict__ out) {
    extern __shared__ __align__(16) float smem[];
    const uint32_t sbase = (uint32_t)__cvta_generic_to_shared(smem);
    char* smc = (char*)smem;

    const int h = blockIdx.x;
    const int b = blockIdx.y;
    const int tid = threadIdx.x;

    const char* x1row = (const char*)(x1 + (long)b * Cc * CHW + (long)h * Ww);
    const char* x2row = (const char*)(x2 + (long)b * Cc * CHW + (long)h * Ww);

    // zero sb pad chunks (cols 0..4 and 85..95 per row) in both buffers:
    // 16 pad chunks/row * 16 rows * 2 bufs = 512 -> 2 per thread
#pragma unroll
    for (int t = 0; t < 2; t++) {
        int z = tid + t * 256;
        int bu = z >> 8, rem = z & 255;
        int row = rem >> 4, k = rem & 15;
        int chunk = (k < 5) ? k : (80 + k);
        *(float4*)(smc + bu * BUF_BY + SA_BY + (row * SB_CHR + swzq(chunk)) * 16)
            = make_float4(0.f, 0.f, 0.f, 0.f);
    }

    // fill addressing: 1280 chunks per tile, 5 per thread
    uint32_t saDst[5], sbDst[5], srcOff[5];
#pragma unroll
    for (int t = 0; t < 5; t++) {
        int idx = tid + 256 * t;
        int r = idx / SA_CHR, c = idx % SA_CHR;
        saDst[t] = sbase + (uint32_t)((r * SA_CHR + swzq(c)) * 16);
        sbDst[t] = sbase + SA_BY + (uint32_t)((r * SB_CHR + swzq(5 + c)) * 16);
        srcOff[t] = (uint32_t)((r * CHW + c * 4) * 4);
    }

    // compute mapping: (d-group g, w-slot ws); warps 0..5 pure-g
    int g, ws;
    bool active;
    if (tid < 192) { g = tid >> 5; ws = tid & 31; active = true; }
    else { int t2 = tid - 192; g = t2 >> 3; ws = 32 + (t2 & 7); active = (t2 < 48); }
    const int w0 = ws * 8;
    const int dbase = g * 8;
    const int qa0 = w0 >> 2;
    const int qb0 = (w0 + dbase) >> 2;

    // loop-invariant swizzled byte offsets (row 0); row strides are
    // multiples of 16 chunks -> swizzle-invariant, added as immediates
    uint32_t aB[2], bB[4];
#pragma unroll
    for (int i = 0; i < 2; i++) aB[i] = (uint32_t)(swzq(qa0 + i) * 16);
#pragma unroll
    for (int i = 0; i < 4; i++) bB[i] = SA_BY + (uint32_t)(swzq(qb0 + i) * 16);

    ull acc[32];
#pragma unroll
    for (int i = 0; i < 32; i++) acc[i] = 0ull;

    // prologue: chunk 0 -> buf 0
#pragma unroll
    for (int t = 0; t < 5; t++) cp16(saDst[t], x1row + srcOff[t]);
#pragma unroll
    for (int t = 0; t < 5; t++) cp16(sbDst[t], x2row + srcOff[t]);
    cp_commit();

    const char* g1 = x1row;
    const char* g2 = x2row;

#pragma unroll 1
    for (int k = 0; k < NCH; k++) {
        cp_wait0();
        __syncthreads();   // chunk k landed; all readers of buf (k+1)&1 done

        if (k + 1 < NCH) {
            g1 += (long)KC * CHW * 4;
            g2 += (long)KC * CHW * 4;
            const uint32_t bo = (uint32_t)(((k + 1) & 1) * BUF_BY);
#pragma unroll
            for (int t = 0; t < 5; t++) cp16(saDst[t] + bo, g1 + srcOff[t]);
#pragma unroll
            for (int t = 0; t < 5; t++) cp16(sbDst[t] + bo, g2 + srcOff[t]);
            cp_commit();
        }

        if (active) {
            const char* base = smc + (k & 1) * BUF_BY;
#pragma unroll
            for (int cc = 0; cc < KC; cc++) {
                const int oa = cc * (SA_CHR * 16);
                const int ob = cc * (SB_CHR * 16);
                ulonglong2 A0 = *(const ulonglong2*)(base + aB[0] + oa);
                ulonglong2 A1 = *(const ulonglong2*)(base + aB[1] + oa);
                LQ B0, B1, B2, B3;
                B0.f = *(const float4*)(base + bB[0] + ob);
                B1.f = *(const float4*)(base + bB[1] + ob);
                B2.f = *(const float4*)(base + bB[2] + ob);
                B3.f = *(const float4*)(base + bB[3] + ob);

                // even pairs are free register pairs; odd pairs pay 2 MOVs
                ull bp0  = B0.u.x;
                ull bp1  = pk2(B0.f.y, B0.f.z);
                ull bp2  = B0.u.y;
                ull bp3  = pk2(B0.f.w, B1.f.x);
                ull bp4  = B1.u.x;
                ull bp5  = pk2(B1.f.y, B1.f.z);
                ull bp6  = B1.u.y;
                ull bp7  = pk2(B1.f.w, B2.f.x);
                ull bp8  = B2.u.x;
                ull bp9  = pk2(B2.f.y, B2.f.z);
                ull bp10 = B2.u.y;
                ull bp11 = pk2(B2.f.w, B3.f.x);
                ull bp12 = B3.u.x;
                ull bp13 = pk2(B3.f.y, B3.f.z);

                // wp = 0 : shifts 0..7
                ffma2(acc[0], A0.x, bp0);  ffma2(acc[1], A0.x, bp1);
                ffma2(acc[2], A0.x, bp2);  ffma2(acc[3], A0.x, bp3);
                ffma2(acc[4], A0.x, bp4);  ffma2(acc[5], A0.x, bp5);
                ffma2(acc[6], A0.x, bp6);  ffma2(acc[7], A0.x, bp7);
                // wp = 1 : shifts 2..9
                ffma2(acc[8],  A0.y, bp2); ffma2(acc[9],  A0.y, bp3);
                ffma2(acc[10], A0.y, bp4); ffma2(acc[11], A0.y, bp5);
                ffma2(acc[12], A0.y, bp6); ffma2(acc[13], A0.y, bp7);
                ffma2(acc[14], A0.y, bp8); ffma2(acc[15], A0.y, bp9);
                // wp = 2 : shifts 4..11
                ffma2(acc[16], A1.x, bp4); ffma2(acc[17], A1.x, bp5);
                ffma2(acc[18], A1.x, bp6); ffma2(acc[19], A1.x, bp7);
                ffma2(acc[20], A1.x, bp8); ffma2(acc[21], A1.x, bp9);
                ffma2(acc[22], A1.x, bp10); ffma2(acc[23], A1.x, bp11);
                // wp = 3 : shifts 6..13
                ffma2(acc[24], A1.y, bp6);  ffma2(acc[25], A1.y, bp7);
                ffma2(acc[26], A1.y, bp8);  ffma2(acc[27], A1.y, bp9);
                ffma2(acc[28], A1.y, bp10); ffma2(acc[29], A1.y, bp11);
                ffma2(acc[30], A1.y, bp12); ffma2(acc[31], A1.y, bp13);
            }
        }
    }

    // epilogue: acc[wp*8+dd] = (out[w0+2wp, dbase+dd], out[w0+2wp+1, dbase+dd])
    if (active) {
#pragma unroll
        for (int dd = 0; dd < 8; dd++) {
            const int d = dbase + dd;
            if (d < Dd) {
                float f[8];
#pragma unroll
                for (int wp = 0; wp < 4; wp++)
                    upk2(acc[wp * 8 + dd], f[2 * wp], f[2 * wp + 1]);
                float* o = out + (((long)b * Dd + d) * Hh + h) * Ww + w0;
                *(float4*)o = make_float4(f[0], f[1], f[2], f[3]);
                *(float4*)(o + 4) = make_float4(f[4], f[5], f[6], f[7]);
            }
        }
    }
}

extern "C" void kernel_launch(void* const* d_in, const int* in_sizes, int n_in,
                              void* d_out, int out_size) {
    const float* x1 = (const float*)d_in[0];
    const float* x2 = (const float*)d_in[1];
    float* out = (float*)d_out;
    cudaFuncSetAttribute(corr1d_kernel,
                         cudaFuncAttributeMaxDynamicSharedMemorySize, 2 * BUF_BY);
    dim3 grid(Hh, 8);
    corr1d_kernel<<<grid, 256, 2 * BUF_BY>>>(x1, x2, out);
}

// round 6
// speedup vs baseline: 1.3702x; 1.3702x over previous
#include <cuda_runtime.h>
#include <cstdint>

// CorrelationLayer1D: out[b,d,h,w] = sum_c x1[b,c,h,w]*x2pad[b,c,h,w+d]
// B=8,C=256,H=96,W=320,D=41. R5: swizzle-invariant strides (WB=384) ->
// zero per-cc address ALU; 1 sync/chunk; union even-pairs (fixed compile).

#define Cc 256
#define Hh 96
#define Ww 320
#define Dd 41
#define KC 16
#define NCH (Cc / KC)
#define CHW (Hh * Ww)
#define WB 384
#define SA_CHR 80
#define SB_CHR 96
#define SA_BY (KC * Ww * 4)     // 20480
#define SB_BY (KC * WB * 4)     // 24576
#define BUF_BY (SA_BY + SB_BY)  // 45056

typedef unsigned long long ull;

static __device__ __forceinline__ ull pk2(float x, float y) {
    ull r; asm("mov.b64 %0, {%1,%2};" : "=l"(r) : "f"(x), "f"(y)); return r;
}
static __device__ __forceinline__ void upk2(ull v, float& x, float& y) {
    asm("mov.b64 {%0,%1}, %2;" : "=f"(x), "=f"(y) : "l"(v));
}
static __device__ __forceinline__ void ffma2(ull& d, ull a, ull b) {
    asm("fma.rn.f32x2 %0, %1, %2, %0;" : "+l"(d) : "l"(a), "l"(b));
}
static __device__ __forceinline__ int swzq(int q) { return q ^ ((q >> 3) & 1); }
static __device__ __forceinline__ void cp16(uint32_t s, const void* g) {
    asm volatile("cp.async.cg.shared.global [%0], [%1], 16;" :: "r"(s), "l"(g));
}
static __device__ __forceinline__ void cp_commit() {
    asm volatile("cp.async.commit_group;");
}
static __device__ __forceinline__ void cp_wait0() {
    asm volatile("cp.async.wait_group 0;");
}

union LQ { float4 f; ulonglong2 u; };

__global__ __launch_bounds__(256, 2)
void corr1d_kernel(const float* __restrict__ x1, const float* __restrict__ x2,
                   float* __restrict__ out) {
    extern __shared__ __align__(16) float smem[];
    const uint32_t sbase = (uint32_t)__cvta_generic_to_shared(smem);
    char* smc = (char*)smem;

    const int h = blockIdx.x;
    const int b = blockIdx.y;
    const int tid = threadIdx.x;

    const char* x1row = (const char*)(x1 + (long)b * Cc * CHW + (long)h * Ww);
    const char* x2row = (const char*)(x2 + (long)b * Cc * CHW + (long)h * Ww);

    // zero sb pad chunks (cols 0..4 and 85..95 per row) in both buffers:
    // 16 pad chunks/row * 16 rows * 2 bufs = 512 -> 2 per thread
#pragma unroll
    for (int t = 0; t < 2; t++) {
        int z = tid + t * 256;
        int bu = z >> 8, rem = z & 255;
        int row = rem >> 4, k = rem & 15;
        int chunk = (k < 5) ? k : (80 + k);
        *(float4*)(smc + bu * BUF_BY + SA_BY + (row * SB_CHR + swzq(chunk)) * 16)
            = make_float4(0.f, 0.f, 0.f, 0.f);
    }

    // fill addressing: 1280 chunks per tile, 5 per thread
    uint32_t saDst[5], sbDst[5], srcOff[5];
#pragma unroll
    for (int t = 0; t < 5; t++) {
        int idx = tid + 256 * t;
        int r = idx / SA_CHR, c = idx % SA_CHR;
        saDst[t] = sbase + (uint32_t)((r * SA_CHR + swzq(c)) * 16);
        sbDst[t] = sbase + SA_BY + (uint32_t)((r * SB_CHR + swzq(5 + c)) * 16);
        srcOff[t] = (uint32_t)((r * CHW + c * 4) * 4);
    }

    // compute mapping: (d-group g, w-slot ws); warps 0..5 pure-g
    int g, ws;
    bool active;
    if (tid < 192) { g = tid >> 5; ws = tid & 31; active = true; }
    else { int t2 = tid - 192; g = t2 >> 3; ws = 32 + (t2 & 7); active = (t2 < 48); }
    const int w0 = ws * 8;
    const int dbase = g * 8;
    const int qa0 = w0 >> 2;
    const int qb0 = (w0 + dbase) >> 2;

    // loop-invariant swizzled byte offsets (row 0); row strides are
    // multiples of 16 chunks -> swizzle-invariant, added as immediates
    uint32_t aB[2], bB[4];
#pragma unroll
    for (int i = 0; i < 2; i++) aB[i] = (uint32_t)(swzq(qa0 + i) * 16);
#pragma unroll
    for (int i = 0; i < 4; i++) bB[i] = SA_BY + (uint32_t)(swzq(qb0 + i) * 16);

    ull acc[32];
#pragma unroll
    for (int i = 0; i < 32; i++) acc[i] = 0ull;

    // prologue: chunk 0 -> buf 0
#pragma unroll
    for (int t = 0; t < 5; t++) cp16(saDst[t], x1row + srcOff[t]);
#pragma unroll
    for (int t = 0; t < 5; t++) cp16(sbDst[t], x2row + srcOff[t]);
    cp_commit();

    const char* g1 = x1row;
    const char* g2 = x2row;

#pragma unroll 1
    for (int k = 0; k < NCH; k++) {
        cp_wait0();
        __syncthreads();   // chunk k landed; all readers of buf (k+1)&1 done

        if (k + 1 < NCH) {
            g1 += (long)KC * CHW * 4;
            g2 += (long)KC * CHW * 4;
            const uint32_t bo = (uint32_t)(((k + 1) & 1) * BUF_BY);
#pragma unroll
            for (int t = 0; t < 5; t++) cp16(saDst[t] + bo, g1 + srcOff[t]);
#pragma unroll
            for (int t = 0; t < 5; t++) cp16(sbDst[t] + bo, g2 + srcOff[t]);
            cp_commit();
        }

        if (active) {
            const char* base = smc + (k & 1) * BUF_BY;
#pragma unroll
            for (int cc = 0; cc < KC; cc++) {
                const int oa = cc * (SA_CHR * 16);
                const int ob = cc * (SB_CHR * 16);
                ulonglong2 A0 = *(const ulonglong2*)(base + aB[0] + oa);
                ulonglong2 A1 = *(const ulonglong2*)(base + aB[1] + oa);
                LQ B0, B1, B2, B3;
                B0.f = *(const float4*)(base + bB[0] + ob);
                B1.f = *(const float4*)(base + bB[1] + ob);
                B2.f = *(const float4*)(base + bB[2] + ob);
                B3.f = *(const float4*)(base + bB[3] + ob);

                // even pairs are free register pairs; odd pairs pay 2 MOVs
                ull bp0  = B0.u.x;
                ull bp1  = pk2(B0.f.y, B0.f.z);
                ull bp2  = B0.u.y;
                ull bp3  = pk2(B0.f.w, B1.f.x);
                ull bp4  = B1.u.x;
                ull bp5  = pk2(B1.f.y, B1.f.z);
                ull bp6  = B1.u.y;
                ull bp7  = pk2(B1.f.w, B2.f.x);
                ull bp8  = B2.u.x;
                ull bp9  = pk2(B2.f.y, B2.f.z);
                ull bp10 = B2.u.y;
                ull bp11 = pk2(B2.f.w, B3.f.x);
                ull bp12 = B3.u.x;
                ull bp13 = pk2(B3.f.y, B3.f.z);

                // wp = 0 : shifts 0..7
                ffma2(acc[0], A0.x, bp0);  ffma2(acc[1], A0.x, bp1);
                ffma2(acc[2], A0.x, bp2);  ffma2(acc[3], A0.x, bp3);
                ffma2(acc[4], A0.x, bp4);  ffma2(acc[5], A0.x, bp5);
                ffma2(acc[6], A0.x, bp6);  ffma2(acc[7], A0.x, bp7);
                // wp = 1 : shifts 2..9
                ffma2(acc[8],  A0.y, bp2); ffma2(acc[9],  A0.y, bp3);
                ffma2(acc[10], A0.y, bp4); ffma2(acc[11], A0.y, bp5);
                ffma2(acc[12], A0.y, bp6); ffma2(acc[13], A0.y, bp7);
                ffma2(acc[14], A0.y, bp8); ffma2(acc[15], A0.y, bp9);
                // wp = 2 : shifts 4..11
                ffma2(acc[16], A1.x, bp4); ffma2(acc[17], A1.x, bp5);
                ffma2(acc[18], A1.x, bp6); ffma2(acc[19], A1.x, bp7);
                ffma2(acc[20], A1.x, bp8); ffma2(acc[21], A1.x, bp9);
                ffma2(acc[22], A1.x, bp10); ffma2(acc[23], A1.x, bp11);
                // wp = 3 : shifts 6..13
                ffma2(acc[24], A1.y, bp6);  ffma2(acc[25], A1.y, bp7);
                ffma2(acc[26], A1.y, bp8);  ffma2(acc[27], A1.y, bp9);
                ffma2(acc[28], A1.y, bp10); ffma2(acc[29], A1.y, bp11);
                ffma2(acc[30], A1.y, bp12); ffma2(acc[31], A1.y, bp13);
            }
        }
    }

    // epilogue: acc[wp*8+dd] = (out[w0+2wp, dbase+dd], out[w0+2wp+1, dbase+dd])
    if (active) {
#pragma unroll
        for (int dd = 0; dd < 8; dd++) {
            const int d = dbase + dd;
            if (d < Dd) {
                float f[8];
#pragma unroll
                for (int wp = 0; wp < 4; wp++)
                    upk2(acc[wp * 8 + dd], f[2 * wp], f[2 * wp + 1]);
                float* o = out + (((long)b * Dd + d) * Hh + h) * Ww + w0;
                *(float4*)o = make_float4(f[0], f[1], f[2], f[3]);
                *(float4*)(o + 4) = make_float4(f[4], f[5], f[6], f[7]);
            }
        }
    }
}

extern "C" void kernel_launch(void* const* d_in, const int* in_sizes, int n_in,
                              void* d_out, int out_size) {
    const float* x1 = (const float*)d_in[0];
    const float* x2 = (const float*)d_in[1];
    float* out = (float*)d_out;
    cudaFuncSetAttribute(corr1d_kernel,
                         cudaFuncAttributeMaxDynamicSharedMemorySize, 2 * BUF_BY);
    dim3 grid(Hh, 8);
    corr1d_kernel<<<grid, 256, 2 * BUF_BY>>>(x1, x2, out);
}

// round 8
// speedup vs baseline: 1.4747x; 1.0762x over previous
#include <cuda_runtime.h>
#include <cuda_bf16.h>
#include <cstdint>

// CorrelationLayer1D via mma.sync (HMMA) bf16-split banded GEMM.
// out[b,d,h,w] = sum_c x1[b,c,h,w] * x2pad[b,c,h,w+d], D=41, MAX_DISP=20.
// CTA = (b,h) row. A[m=w][k=c] (x1), B[n=j][k=c] (x2pad, j = w'+20, 360 wide).
// Warp = m-tile of 16; 7 n-tiles of 8 cover the 56-wide band.
// fp32 -> bf16 hi+lo; D = AhBh + AlBh + AhBl (fp32 accum). rel err ~1e-5.

#define Cc 256
#define Hh 96
#define Ww 320
#define Dd 41
#define CHW (Hh * Ww)
#define KC 16
#define NCH 16
#define PITCH 36                      // bytes per k-row (32B data + 4 pad)
#define SA_LO (320 * PITCH)           // 11520
#define SB_HI (2 * 320 * PITCH)       // 23040
#define SB_D  (360 * PITCH)           // 12960 (hi->lo offset within SB)
#define BUFB  (SB_HI + 2 * SB_D)      // 48960
#define SMEMB (2 * BUFB)              // 97920
#define BP 43                          // band pitch (words)

typedef uint32_t u32;

static __device__ __forceinline__ void split2(float v0, float v1, u32& hi, u32& lo) {
    __nv_bfloat16 h0 = __float2bfloat16(v0), h1 = __float2bfloat16(v1);
    __nv_bfloat16 l0 = __float2bfloat16(v0 - __bfloat162float(h0));
    __nv_bfloat16 l1 = __float2bfloat16(v1 - __bfloat162float(h1));
    hi = (u32)__bfloat16_as_ushort(h0) | ((u32)__bfloat16_as_ushort(h1) << 16);
    lo = (u32)__bfloat16_as_ushort(l0) | ((u32)__bfloat16_as_ushort(l1) << 16);
}

static __device__ __forceinline__ void mma16816(float* c, const u32* a, const u32* b) {
    asm volatile(
        "mma.sync.aligned.m16n8k16.row.col.f32.bf16.bf16.f32 "
        "{%0,%1,%2,%3},{%4,%5,%6,%7},{%8,%9},{%0,%1,%2,%3};"
        : "+f"(c[0]), "+f"(c[1]), "+f"(c[2]), "+f"(c[3])
        : "r"(a[0]), "r"(a[1]), "r"(a[2]), "r"(a[3]), "r"(b[0]), "r"(b[1]));
}

__global__ __launch_bounds__(640, 1)
void corr1d_hmma(const float* __restrict__ x1, const float* __restrict__ x2,
                 float* __restrict__ out) {
    extern __shared__ __align__(16) char sm[];
    const int tid = threadIdx.x, wid = tid >> 5, lid = tid & 31;
    const int g = lid >> 2, tg = lid & 3;
    const int h = blockIdx.x, b = blockIdx.y;

    const float* X1 = x1 + ((size_t)b * Cc) * CHW + (size_t)h * Ww;
    const float* X2 = x2 + ((size_t)b * Cc) * CHW + (size_t)h * Ww;

    // ---- fill task decomposition (per chunk of KC=16 channels) ----
    // x1: 1280 tasks (w, c4): it in {0,1}: w = tid%320, c4 = 2*it + tid/320
    // x2: 1440 tasks (j, c4): it in {0,1,2}: tt = tid + 640*it
    const int wa = tid % 320, c4a = tid / 320;
    int jb[3], c4b[3], wpb[3];
    bool vb[3];
#pragma unroll
    for (int it = 0; it < 3; it++) {
        int tt = tid + 640 * it;
        vb[it] = tt < 1440;
        int j = tt % 360;
        jb[it] = j; c4b[it] = tt / 360; wpb[it] = j - 20;
    }

    float r1[2][4], r2[3][4];

    // prologue: LDG chunk 0
    {
        const float* p1 = X1;
        const float* p2 = X2;
#pragma unroll
        for (int it = 0; it < 2; it++) {
            int c4 = 2 * it + c4a;
#pragma unroll
            for (int e = 0; e < 4; e++)
                r1[it][e] = p1[(size_t)(4 * c4 + e) * CHW + wa];
        }
#pragma unroll
        for (int it = 0; it < 3; it++) {
            bool ok = vb[it] && wpb[it] >= 0 && wpb[it] < Ww;
#pragma unroll
            for (int e = 0; e < 4; e++)
                r2[it][e] = ok ? p2[(size_t)(4 * c4b[it] + e) * CHW + wpb[it]] : 0.0f;
        }
    }

    // ---- fragment addresses (byte offsets within a buffer) ----
    const int w0 = wid * 16;
    const u32 aoff = (u32)((w0 + g) * PITCH + 4 * tg);

    float acc[7][4];
#pragma unroll
    for (int nt = 0; nt < 7; nt++)
#pragma unroll
        for (int i = 0; i < 4; i++) acc[nt][i] = 0.0f;

#pragma unroll 1
    for (int kk = 0; kk < NCH; kk++) {
        char* buf = sm + (kk & 1) * BUFB;

        // STS: staged regs -> buf (split to bf16 hi/lo)
#pragma unroll
        for (int it = 0; it < 2; it++) {
            int c4 = 2 * it + c4a;
            u32 off = (u32)(wa * PITCH + 8 * c4);
            u32 hi, lo;
            split2(r1[it][0], r1[it][1], hi, lo);
            *(u32*)(buf + off) = hi;
            *(u32*)(buf + SA_LO + off) = lo;
            split2(r1[it][2], r1[it][3], hi, lo);
            *(u32*)(buf + off + 4) = hi;
            *(u32*)(buf + SA_LO + off + 4) = lo;
        }
#pragma unroll
        for (int it = 0; it < 3; it++) {
            if (vb[it]) {
                u32 off = (u32)(SB_HI + jb[it] * PITCH + 8 * c4b[it]);
                u32 hi, lo;
                split2(r2[it][0], r2[it][1], hi, lo);
                *(u32*)(buf + off) = hi;
                *(u32*)(buf + SB_D + off) = lo;
                split2(r2[it][2], r2[it][3], hi, lo);
                *(u32*)(buf + off + 4) = hi;
                *(u32*)(buf + SB_D + off + 4) = lo;
            }
        }

        // LDG next chunk (latency hides under this chunk's mma)
        if (kk + 1 < NCH) {
            const float* p1 = X1 + (size_t)(kk + 1) * KC * CHW;
            const float* p2 = X2 + (size_t)(kk + 1) * KC * CHW;
#pragma unroll
            for (int it = 0; it < 2; it++) {
                int c4 = 2 * it + c4a;
#pragma unroll
                for (int e = 0; e < 4; e++)
                    r1[it][e] = p1[(size_t)(4 * c4 + e) * CHW + wa];
            }
#pragma unroll
            for (int it = 0; it < 3; it++) {
                bool ok = vb[it] && wpb[it] >= 0 && wpb[it] < Ww;
#pragma unroll
                for (int e = 0; e < 4; e++)
                    r2[it][e] = ok ? p2[(size_t)(4 * c4b[it] + e) * CHW + wpb[it]] : 0.0f;
            }
        }

        __syncthreads();   // buf is filled; other buffer free for next STS

        // mma on buf
        u32 ah[4], al[4];
        ah[0] = *(const u32*)(buf + aoff);
        ah[1] = *(const u32*)(buf + aoff + 8 * PITCH);
        ah[2] = *(const u32*)(buf + aoff + 16);
        ah[3] = *(const u32*)(buf + aoff + 8 * PITCH + 16);
        al[0] = *(const u32*)(buf + SA_LO + aoff);
        al[1] = *(const u32*)(buf + SA_LO + aoff + 8 * PITCH);
        al[2] = *(const u32*)(buf + SA_LO + aoff + 16);
        al[3] = *(const u32*)(buf + SA_LO + aoff + 8 * PITCH + 16);
#pragma unroll
        for (int nt = 0; nt < 7; nt++) {
            u32 boff = (u32)(SB_HI + (w0 + 8 * nt + g) * PITCH + 4 * tg);
            u32 bh[2], bl[2];
            bh[0] = *(const u32*)(buf + boff);
            bh[1] = *(const u32*)(buf + boff + 16);
            bl[0] = *(const u32*)(buf + SB_D + boff);
            bl[1] = *(const u32*)(buf + SB_D + boff + 16);
            mma16816(acc[nt], ah, bh);
            mma16816(acc[nt], al, bh);
            mma16816(acc[nt], ah, bl);
        }
    }

    __syncthreads();

    // ---- band stage: band[m][d] = D[m][m+d], pitch BP words ----
    float* band = (float*)sm;
#pragma unroll
    for (int nt = 0; nt < 7; nt++) {
        int jl = 8 * nt + 2 * tg;
        int d0 = jl - g;         // r = g      (c0, c1)
        int d2 = jl - g - 8;     // r = g + 8  (c2, c3)
        if (d0 >= 0 && d0 < Dd)     band[(w0 + g) * BP + d0] = acc[nt][0];
        if (d0 + 1 >= 0 && d0 + 1 < Dd) band[(w0 + g) * BP + d0 + 1] = acc[nt][1];
        if (d2 >= 0 && d2 < Dd)     band[(w0 + g + 8) * BP + d2] = acc[nt][2];
        if (d2 + 1 >= 0 && d2 + 1 < Dd) band[(w0 + g + 8) * BP + d2 + 1] = acc[nt][3];
    }
    __syncthreads();

    // ---- coalesced output: out[d][w] = band[w][d] ----
    const int w = tid % 320;
    float* ob = out + ((size_t)b * Dd * Hh + h) * Ww + w;
#pragma unroll 1
    for (int d = tid / 320; d < Dd; d += 2)
        ob[(size_t)d * Hh * Ww] = band[w * BP + d];
}

extern "C" void kernel_launch(void* const* d_in, const int* in_sizes, int n_in,
                              void* d_out, int out_size) {
    const float* x1 = (const float*)d_in[0];
    const float* x2 = (const float*)d_in[1];
    float* out = (float*)d_out;
    cudaFuncSetAttribute(corr1d_hmma,
                         cudaFuncAttributeMaxDynamicSharedMemorySize, SMEMB);
    dim3 grid(Hh, 8);
    corr1d_hmma<<<grid, 640, SMEMB>>>(x1, x2, out);
}

// round 9
// speedup vs baseline: 1.9897x; 1.3493x over previous
#include <cuda_runtime.h>
#include <cuda_bf16.h>
#include <cstdint>

// CorrelationLayer1D via HMMA bf16-split banded GEMM, v2.
// CTA = 320 thr, half-row (160 w). A[m=w][k=c] (x1, 160 rows),
// B[j][k] (x2pad window, 200 rows, j -> w' = W0+j-20). Warp = m-tile 16,
// 7 n-tiles of 8 at nB = m0+8nt. D = AhBh + AlBh + AhBl (fp32 acc).
// smem: 32B rows, planes hi/lo, XOR-16B swizzle; ldmatrix fragments.

#define Cc 256
#define Hh 96
#define Ww 320
#define Dd 41
#define CHW (Hh * Ww)
#define NCH 16
#define MR 160
#define NR 200
#define A_HI 0
#define A_LO 5120
#define B_HI 10240
#define B_LO 16640
#define BUFB 23040
#define SMEMB (2 * BUFB + 1024)
#define BP 43

typedef uint32_t u32;

static __device__ __forceinline__ u32 swz16(int q) {
    return (u32)((q ^ ((q >> 3) & 1)) * 16);
}
static __device__ __forceinline__ void split2(float v0, float v1, u32& hi, u32& lo) {
    __nv_bfloat16 h0 = __float2bfloat16(v0), h1 = __float2bfloat16(v1);
    __nv_bfloat16 l0 = __float2bfloat16(v0 - __bfloat162float(h0));
    __nv_bfloat16 l1 = __float2bfloat16(v1 - __bfloat162float(h1));
    hi = (u32)__bfloat16_as_ushort(h0) | ((u32)__bfloat16_as_ushort(h1) << 16);
    lo = (u32)__bfloat16_as_ushort(l0) | ((u32)__bfloat16_as_ushort(l1) << 16);
}
static __device__ __forceinline__ void mma16816(float* c, const u32* a, const u32* b) {
    asm volatile(
        "mma.sync.aligned.m16n8k16.row.col.f32.bf16.bf16.f32 "
        "{%0,%1,%2,%3},{%4,%5,%6,%7},{%8,%9},{%0,%1,%2,%3};"
        : "+f"(c[0]), "+f"(c[1]), "+f"(c[2]), "+f"(c[3])
        : "r"(a[0]), "r"(a[1]), "r"(a[2]), "r"(a[3]), "r"(b[0]), "r"(b[1]));
}
static __device__ __forceinline__ void ldsm4(u32* r, u32 a) {
    asm volatile("ldmatrix.sync.aligned.m8n8.x4.shared.b16 {%0,%1,%2,%3},[%4];"
                 : "=r"(r[0]), "=r"(r[1]), "=r"(r[2]), "=r"(r[3]) : "r"(a));
}
static __device__ __forceinline__ void ldsm2(u32* r, u32 a) {
    asm volatile("ldmatrix.sync.aligned.m8n8.x2.shared.b16 {%0,%1},[%2];"
                 : "=r"(r[0]), "=r"(r[1]) : "r"(a));
}
static __device__ __forceinline__ void st128(char* p, u32 a, u32 b, u32 c, u32 d) {
    *(uint4*)p = make_uint4(a, b, c, d);
}

__global__ __launch_bounds__(320, 2)
void corr1d_hmma2(const float* __restrict__ x1, const float* __restrict__ x2,
                  float* __restrict__ out) {
    extern __shared__ __align__(16) char sm[];
    const int tid = threadIdx.x, wid = tid >> 5, lid = tid & 31;
    const int g = lid >> 2, tg = lid & 3;
    const int wt = blockIdx.x, h = blockIdx.y, b = blockIdx.z;
    const int W0 = wt * 160;
    const u32 sbase = (u32)__cvta_generic_to_shared(sm);

    const float* X1 = x1 + ((size_t)b * Cc) * CHW + (size_t)h * Ww;
    const float* X2 = x2 + ((size_t)b * Cc) * CHW + (size_t)h * Ww;

    // ---- fill tasks: A 320 = (j 0..159, h 0..1); B 400 = (j 0..199, h 0..1)
    const int jA = tid % 160, hA = tid / 160;
    const int jB0 = (tid < 200) ? tid : tid - 200;
    const int hB0 = (tid < 200) ? 0 : 1;
    const int jB1 = tid + 120;                 // h = 1
    const bool vB1 = (tid < 80);
    const int wp0 = W0 + jB0 - 20, wp1 = W0 + jB1 - 20;
    const bool ok0 = (wp0 >= 0 && wp0 < Ww);
    const bool ok1 = vB1 && (wp1 >= 0 && wp1 < Ww);

    const float* pA = X1 + W0 + jA + (size_t)hA * 8 * CHW;
    const float* pB0 = X2 + (ok0 ? wp0 : 0) + (size_t)hB0 * 8 * CHW;
    const float* pB1 = X2 + (ok1 ? wp1 : 0) + (size_t)8 * CHW;

    const u32 stA = swz16(2 * jA + hA);
    const u32 stB0 = swz16(2 * jB0 + hB0);
    const u32 stB1 = swz16(2 * jB1 + 1);

    // ---- fragment lane offsets (ldmatrix) ----
    const int m0 = wid * 16;
    const u32 offA = swz16(2 * (m0 + (lid & 15)) + (lid >> 4));
    const u32 offB = swz16(2 * (m0 + (lid & 7) + 8 * (lid >> 4)) + ((lid >> 3) & 1));
    int n6 = m0 + 48 + (lid & 7) + 8 * (lid >> 4);
    if (n6 > NR - 1) n6 = NR - 1;               // lanes 16..31 unused by x2
    const u32 offB6 = swz16(2 * n6 + ((lid >> 3) & 1));

    float rA[8], rB0[8], rB1[8];
#pragma unroll
    for (int e = 0; e < 8; e++) {
        rA[e] = pA[(size_t)e * CHW];
        rB0[e] = ok0 ? pB0[(size_t)e * CHW] : 0.0f;
        rB1[e] = ok1 ? pB1[(size_t)e * CHW] : 0.0f;
    }

    float acc[7][4];
#pragma unroll
    for (int nt = 0; nt < 7; nt++)
#pragma unroll
        for (int i = 0; i < 4; i++) acc[nt][i] = 0.0f;

#pragma unroll 1
    for (int kk = 0; kk < NCH; kk++) {
        char* bufc = sm + (kk & 1) * BUFB;
        const u32 bufs = sbase + (u32)((kk & 1) * BUFB);

        // STS (split to bf16 hi/lo, STS.128 per 16B chunk)
        {
            u32 h0, h1, h2, h3, l0, l1, l2, l3;
            split2(rA[0], rA[1], h0, l0); split2(rA[2], rA[3], h1, l1);
            split2(rA[4], rA[5], h2, l2); split2(rA[6], rA[7], h3, l3);
            st128(bufc + A_HI + stA, h0, h1, h2, h3);
            st128(bufc + A_LO + stA, l0, l1, l2, l3);
            split2(rB0[0], rB0[1], h0, l0); split2(rB0[2], rB0[3], h1, l1);
            split2(rB0[4], rB0[5], h2, l2); split2(rB0[6], rB0[7], h3, l3);
            st128(bufc + B_HI + stB0, h0, h1, h2, h3);
            st128(bufc + B_LO + stB0, l0, l1, l2, l3);
            if (vB1) {
                split2(rB1[0], rB1[1], h0, l0); split2(rB1[2], rB1[3], h1, l1);
                split2(rB1[4], rB1[5], h2, l2); split2(rB1[6], rB1[7], h3, l3);
                st128(bufc + B_HI + stB1, h0, h1, h2, h3);
                st128(bufc + B_LO + stB1, l0, l1, l2, l3);
            }
        }

        // LDG next chunk
        if (kk + 1 < NCH) {
            pA += (size_t)16 * CHW; pB0 += (size_t)16 * CHW; pB1 += (size_t)16 * CHW;
#pragma unroll
            for (int e = 0; e < 8; e++) {
                rA[e] = pA[(size_t)e * CHW];
                rB0[e] = ok0 ? pB0[(size_t)e * CHW] : 0.0f;
                rB1[e] = ok1 ? pB1[(size_t)e * CHW] : 0.0f;
            }
        }

        __syncthreads();

        // fragments + mma
        u32 ah[4], al[4];
        ldsm4(ah, bufs + A_HI + offA);
        ldsm4(al, bufs + A_LO + offA);
#pragma unroll
        for (int p = 0; p < 3; p++) {
            u32 bh[4], bl[4];
            ldsm4(bh, bufs + B_HI + offB + 512u * p);
            ldsm4(bl, bufs + B_LO + offB + 512u * p);
            mma16816(acc[2 * p], ah, bh);
            mma16816(acc[2 * p + 1], ah, bh + 2);
            mma16816(acc[2 * p], al, bh);
            mma16816(acc[2 * p + 1], al, bh + 2);
            mma16816(acc[2 * p], ah, bl);
            mma16816(acc[2 * p + 1], ah, bl + 2);
        }
        u32 b6h[2], b6l[2];
        ldsm2(b6h, bufs + B_HI + offB6);
        ldsm2(b6l, bufs + B_LO + offB6);
        mma16816(acc[6], ah, b6h);
        mma16816(acc[6], al, b6h);
        mma16816(acc[6], ah, b6l);
    }

    __syncthreads();

    // ---- band stage: band[m][d] = D[m][m0-rel j], pitch BP ----
    float* band = (float*)sm;
#pragma unroll
    for (int nt = 0; nt < 7; nt++) {
        int jl = 8 * nt + 2 * tg;
        int d0 = jl - g;
        int d2 = jl - g - 8;
        if (d0 >= 0 && d0 < Dd) band[(m0 + g) * BP + d0] = acc[nt][0];
        if (d0 + 1 >= 0 && d0 + 1 < Dd) band[(m0 + g) * BP + d0 + 1] = acc[nt][1];
        if (d2 >= 0 && d2 < Dd) band[(m0 + g + 8) * BP + d2] = acc[nt][2];
        if (d2 + 1 >= 0 && d2 + 1 < Dd) band[(m0 + g + 8) * BP + d2 + 1] = acc[nt][3];
    }
    __syncthreads();

    // ---- coalesced output ----
    const int w = tid % 160;
    float* ob = out + ((size_t)b * Dd * Hh + h) * Ww + W0 + w;
#pragma unroll 1
    for (int d = tid / 160; d < Dd; d += 2)
        ob[(size_t)d * Hh * Ww] = band[w * BP + d];
}

extern "C" void kernel_launch(void* const* d_in, const int* in_sizes, int n_in,
                              void* d_out, int out_size) {
    const float* x1 = (const float*)d_in[0];
    const float* x2 = (const float*)d_in[1];
    float* out = (float*)d_out;
    cudaFuncSetAttribute(corr1d_hmma2,
                         cudaFuncAttributeMaxDynamicSharedMemorySize, SMEMB);
    dim3 grid(2, Hh, 8);
    corr1d_hmma2<<<grid, 320, SMEMB>>>(x1, x2, out);
}

// round 11
// speedup vs baseline: 2.2999x; 1.1559x over previous
#include <cuda_runtime.h>
#include <cuda_bf16.h>
#include <cstdint>

// CorrelationLayer1D via HMMA bf16-split banded GEMM, v3b.
// cp.async fp32 staging ring (depth 2) + fast bf16x2 split + ldmatrix.
// CTA = 320 thr, half-row (160 w). Warp = m-tile 16, 7 n-tiles of 8.
// D = AhBh + AlBh + AhBl (fp32 acc), rel err ~5e-6.
// v3b fix: ping-pong destinations computed as absolute slot base + rel offset.

#define Cc 256
#define Hh 96
#define Ww 320
#define Dd 41
#define CHW (Hh * Ww)
#define NCH 16
#define STG_A 0
#define STG_B 20480
#define SLOT_A 10240
#define SLOT_B 12800
#define BF16 46080
#define A_HI 0
#define A_LO 5120
#define B_HI 10240
#define B_LO 16640
#define BUFB 23040
#define SMEMB (BF16 + 2 * BUFB)   // 92160
#define BP 43

typedef uint32_t u32;

static __device__ __forceinline__ u32 swz16(int q) {
    return (u32)((q ^ ((q >> 3) & 1)) * 16);
}
static __device__ __forceinline__ u32 cvt2(float lo, float hi) {
    u32 r; asm("cvt.rn.bf16x2.f32 %0,%1,%2;" : "=r"(r) : "f"(hi), "f"(lo));
    return r;
}
static __device__ __forceinline__ void fsplit(float v0, float v1, u32& hi, u32& lo) {
    hi = cvt2(v0, v1);
    float h0 = __uint_as_float(hi << 16);
    float h1 = __uint_as_float(hi & 0xFFFF0000u);
    lo = cvt2(v0 - h0, v1 - h1);
}
static __device__ __forceinline__ void mma16816(float* c, const u32* a, const u32* b) {
    asm volatile(
        "mma.sync.aligned.m16n8k16.row.col.f32.bf16.bf16.f32 "
        "{%0,%1,%2,%3},{%4,%5,%6,%7},{%8,%9},{%0,%1,%2,%3};"
        : "+f"(c[0]), "+f"(c[1]), "+f"(c[2]), "+f"(c[3])
        : "r"(a[0]), "r"(a[1]), "r"(a[2]), "r"(a[3]), "r"(b[0]), "r"(b[1]));
}
static __device__ __forceinline__ void ldsm4(u32* r, u32 a) {
    asm volatile("ldmatrix.sync.aligned.m8n8.x4.shared.b16 {%0,%1,%2,%3},[%4];"
                 : "=r"(r[0]), "=r"(r[1]), "=r"(r[2]), "=r"(r[3]) : "r"(a));
}
static __device__ __forceinline__ void ldsm2(u32* r, u32 a) {
    asm volatile("ldmatrix.sync.aligned.m8n8.x2.shared.b16 {%0,%1},[%2];"
                 : "=r"(r[0]), "=r"(r[1]) : "r"(a));
}
static __device__ __forceinline__ void cp16(u32 s, const void* g) {
    asm volatile("cp.async.cg.shared.global [%0],[%1],16;" :: "r"(s), "l"(g));
}
static __device__ __forceinline__ void cpcommit() {
    asm volatile("cp.async.commit_group;");
}

__global__ __launch_bounds__(320, 2)
void corr1d_hmma3(const float* __restrict__ x1, const float* __restrict__ x2,
                  float* __restrict__ out) {
    extern __shared__ __align__(16) char sm[];
    const int tid = threadIdx.x, wid = tid >> 5, lid = tid & 31;
    const int g = lid >> 2, tg = lid & 3;
    const int wt = blockIdx.x, h = blockIdx.y, b = blockIdx.z;
    const int W0 = wt * 160;
    const u32 sbase = (u32)__cvta_generic_to_shared(sm);

    const float* X1 = x1 + ((size_t)b * Cc) * CHW + (size_t)h * Ww;
    const float* X2 = x2 + ((size_t)b * Cc) * CHW + (size_t)h * Ww;

    // ---- cp.async tasks ----
    // A: 640 chunks (c 0..15, wq 0..39), 2/thread. rel offsets within a slot.
    const float* gsA[2]; u32 raA[2];
#pragma unroll
    for (int t = 0; t < 2; t++) {
        int idx = tid + 320 * t, c = idx / 40, wq = idx % 40;
        gsA[t] = X1 + (size_t)c * CHW + W0 + 4 * wq;
        raA[t] = (u32)(c * 640 + wq * 16);
    }
    // B: 800 chunks (c 0..15, q 0..49), w = W0-20+4q, <=3/thread
    const float* gsB[3]; u32 raB[3]; bool okB[3];
#pragma unroll
    for (int t = 0; t < 3; t++) {
        int idx = tid + 320 * t, c = idx / 50, q = idx % 50;
        int w = W0 - 20 + 4 * q;
        okB[t] = (idx < 800) && (w >= 0) && (w + 3 < Ww);
        gsB[t] = X2 + (size_t)(c < 16 ? c : 15) * CHW + (okB[t] ? w : 0);
        raB[t] = (u32)((c < 16 ? c : 15) * 800 + q * 16);
    }
    // pre-zero static OOB staging chunks (5 per c-row per slot)
    if (tid < 160) {
        int slot = tid / 80, rem = tid % 80, r = rem / 5;
        int qz = rem % 5 + (wt ? 45 : 0);
        *(uint4*)(sm + STG_B + slot * SLOT_B + r * 800 + qz * 16) =
            make_uint4(0, 0, 0, 0);
    }

    // ---- fill read-back tasks ----
    const int jA = tid % 160, hA = tid / 160;
    const int jB0 = (tid < 200) ? tid : tid - 200;
    const int hB0 = (tid < 200) ? 0 : 1;
    const int jB1 = tid + 120;
    const bool vB1 = (tid < 80);
    const u32 stA = swz16(2 * jA + hA);
    const u32 stB0 = swz16(2 * jB0 + hB0);
    const u32 stB1 = swz16(2 * jB1 + 1);

    // ---- fragment lane offsets ----
    const int m0 = wid * 16;
    const u32 offA = swz16(2 * (m0 + (lid & 15)) + (lid >> 4));
    const u32 offB = swz16(2 * (m0 + (lid & 7) + 8 * (lid >> 4)) + ((lid >> 3) & 1));
    int n6 = m0 + 48 + (lid & 7) + 8 * (lid >> 4);
    if (n6 > 199) n6 = 199;
    const u32 offB6 = swz16(2 * n6 + ((lid >> 3) & 1));

    float acc[7][4];
#pragma unroll
    for (int nt = 0; nt < 7; nt++)
#pragma unroll
        for (int i = 0; i < 4; i++) acc[nt][i] = 0.0f;

    // prologue: chunk 0 -> slot 0
#pragma unroll
    for (int t = 0; t < 2; t++) cp16(sbase + STG_A + raA[t], gsA[t]);
#pragma unroll
    for (int t = 0; t < 3; t++) if (okB[t]) cp16(sbase + STG_B + raB[t], gsB[t]);
    cpcommit();

#pragma unroll 1
    for (int kk = 0; kk < NCH; kk++) {
        const int slot = kk & 1;
        if (kk + 1 < NCH) {
            const u32 baseA = sbase + STG_A + (u32)((slot ^ 1) * SLOT_A);
            const u32 baseB = sbase + STG_B + (u32)((slot ^ 1) * SLOT_B);
#pragma unroll
            for (int t = 0; t < 2; t++) {
                gsA[t] += (size_t)16 * CHW;
                cp16(baseA + raA[t], gsA[t]);
            }
#pragma unroll
            for (int t = 0; t < 3; t++) {
                gsB[t] += (size_t)16 * CHW;
                if (okB[t]) cp16(baseB + raB[t], gsB[t]);
            }
            cpcommit();
            asm volatile("cp.async.wait_group 1;");
        } else {
            asm volatile("cp.async.wait_group 0;");
        }
        __syncthreads();   // chunk kk staging visible

        // fill: LDS staging -> split -> STS bf16 planes
        char* bufc = sm + BF16 + slot * BUFB;
        const float* sgA = (const float*)(sm + STG_A + slot * SLOT_A);
        const float* sgB = (const float*)(sm + STG_B + slot * SLOT_B);
        {
            float v[8]; u32 h0, h1, h2, h3, l0, l1, l2, l3;
#pragma unroll
            for (int e = 0; e < 8; e++) v[e] = sgA[(hA * 8 + e) * 160 + jA];
            fsplit(v[0], v[1], h0, l0); fsplit(v[2], v[3], h1, l1);
            fsplit(v[4], v[5], h2, l2); fsplit(v[6], v[7], h3, l3);
            *(uint4*)(bufc + A_HI + stA) = make_uint4(h0, h1, h2, h3);
            *(uint4*)(bufc + A_LO + stA) = make_uint4(l0, l1, l2, l3);
#pragma unroll
            for (int e = 0; e < 8; e++) v[e] = sgB[(hB0 * 8 + e) * 200 + jB0];
            fsplit(v[0], v[1], h0, l0); fsplit(v[2], v[3], h1, l1);
            fsplit(v[4], v[5], h2, l2); fsplit(v[6], v[7], h3, l3);
            *(uint4*)(bufc + B_HI + stB0) = make_uint4(h0, h1, h2, h3);
            *(uint4*)(bufc + B_LO + stB0) = make_uint4(l0, l1, l2, l3);
            if (vB1) {
#pragma unroll
                for (int e = 0; e < 8; e++) v[e] = sgB[(8 + e) * 200 + jB1];
                fsplit(v[0], v[1], h0, l0); fsplit(v[2], v[3], h1, l1);
                fsplit(v[4], v[5], h2, l2); fsplit(v[6], v[7], h3, l3);
                *(uint4*)(bufc + B_HI + stB1) = make_uint4(h0, h1, h2, h3);
                *(uint4*)(bufc + B_LO + stB1) = make_uint4(l0, l1, l2, l3);
            }
        }
        __syncthreads();   // bf16 planes ready

        // fragments + mma
        const u32 bufs = sbase + BF16 + (u32)(slot * BUFB);
        u32 ah[4], al[4];
        ldsm4(ah, bufs + A_HI + offA);
        ldsm4(al, bufs + A_LO + offA);
#pragma unroll
        for (int p = 0; p < 3; p++) {
            u32 bh[4], bl[4];
            ldsm4(bh, bufs + B_HI + offB + 512u * p);
            ldsm4(bl, bufs + B_LO + offB + 512u * p);
            mma16816(acc[2 * p], ah, bh);
            mma16816(acc[2 * p + 1], ah, bh + 2);
            mma16816(acc[2 * p], al, bh);
            mma16816(acc[2 * p + 1], al, bh + 2);
            mma16816(acc[2 * p], ah, bl);
            mma16816(acc[2 * p + 1], ah, bl + 2);
        }
        u32 b6h[2], b6l[2];
        ldsm2(b6h, bufs + B_HI + offB6);
        ldsm2(b6l, bufs + B_LO + offB6);
        mma16816(acc[6], ah, b6h);
        mma16816(acc[6], al, b6h);
        mma16816(acc[6], ah, b6l);
    }

    __syncthreads();

    // ---- band stage: band[m][d] = D[m][j], d = j - m (m local) ----
    float* band = (float*)sm;
#pragma unroll
    for (int nt = 0; nt < 7; nt++) {
        int jl = 8 * nt + 2 * tg;
        int d0 = jl - g, d2 = jl - g - 8;
        if (d0 >= 0 && d0 < Dd) band[(m0 + g) * BP + d0] = acc[nt][0];
        if (d0 + 1 >= 0 && d0 + 1 < Dd) band[(m0 + g) * BP + d0 + 1] = acc[nt][1];
        if (d2 >= 0 && d2 < Dd) band[(m0 + g + 8) * BP + d2] = acc[nt][2];
        if (d2 + 1 >= 0 && d2 + 1 < Dd) band[(m0 + g + 8) * BP + d2 + 1] = acc[nt][3];
    }
    __syncthreads();

    const int w = tid % 160;
    float* ob = out + ((size_t)b * Dd * Hh + h) * Ww + W0 + w;
#pragma unroll 1
    for (int d = tid / 160; d < Dd; d += 2)
        ob[(size_t)d * Hh * Ww] = band[w * BP + d];
}

extern "C" void kernel_launch(void* const* d_in, const int* in_sizes, int n_in,
                              void* d_out, int out_size) {
    const float* x1 = (const float*)d_in[0];
    const float* x2 = (const float*)d_in[1];
    float* out = (float*)d_out;
    cudaFuncSetAttribute(corr1d_hmma3,
                         cudaFuncAttributeMaxDynamicSharedMemorySize, SMEMB);
    dim3 grid(2, Hh, 8);
    corr1d_hmma3<<<grid, 320, SMEMB>>>(x1, x2, out);
}

// round 12
// speedup vs baseline: 2.3706x; 1.0308x over previous
#include <cuda_runtime.h>
#include <cuda_bf16.h>
#include <cstdint>

// CorrelationLayer1D via HMMA bf16-split banded GEMM, v4.
// v3b + A fragments loaded directly from fp32 staging (conflict-free pitch 164),
// split in registers; B keeps shared bf16 smem planes. smem 92KB -> 72KB.

#define Cc 256
#define Hh 96
#define Ww 320
#define Dd 41
#define CHW (Hh * Ww)
#define NCH 16
#define PA 164                     // A staging pitch in floats (656B rows)
#define SLOT_A 10496               // 16 * 656
#define STG_B 20992                // 2 * SLOT_A
#define SLOT_B 12800
#define BPL 46592                  // STG_B + 2*SLOT_B : bf16 B planes base
#define PLB 12800                  // per-buffer: hi(6400) + lo(6400)
#define B_LO 6400
#define SMEMB (BPL + 2 * PLB)      // 72192
#define BP 43

typedef uint32_t u32;

static __device__ __forceinline__ u32 swz16(int q) {
    return (u32)((q ^ ((q >> 3) & 1)) * 16);
}
static __device__ __forceinline__ u32 cvt2(float lo, float hi) {
    u32 r; asm("cvt.rn.bf16x2.f32 %0,%1,%2;" : "=r"(r) : "f"(hi), "f"(lo));
    return r;
}
static __device__ __forceinline__ void fsplit(float v0, float v1, u32& hi, u32& lo) {
    hi = cvt2(v0, v1);
    float h0 = __uint_as_float(hi << 16);
    float h1 = __uint_as_float(hi & 0xFFFF0000u);
    lo = cvt2(v0 - h0, v1 - h1);
}
static __device__ __forceinline__ void mma16816(float* c, const u32* a, const u32* b) {
    asm volatile(
        "mma.sync.aligned.m16n8k16.row.col.f32.bf16.bf16.f32 "
        "{%0,%1,%2,%3},{%4,%5,%6,%7},{%8,%9},{%0,%1,%2,%3};"
        : "+f"(c[0]), "+f"(c[1]), "+f"(c[2]), "+f"(c[3])
        : "r"(a[0]), "r"(a[1]), "r"(a[2]), "r"(a[3]), "r"(b[0]), "r"(b[1]));
}
static __device__ __forceinline__ void ldsm4(u32* r, u32 a) {
    asm volatile("ldmatrix.sync.aligned.m8n8.x4.shared.b16 {%0,%1,%2,%3},[%4];"
                 : "=r"(r[0]), "=r"(r[1]), "=r"(r[2]), "=r"(r[3]) : "r"(a));
}
static __device__ __forceinline__ void ldsm2(u32* r, u32 a) {
    asm volatile("ldmatrix.sync.aligned.m8n8.x2.shared.b16 {%0,%1},[%2];"
                 : "=r"(r[0]), "=r"(r[1]) : "r"(a));
}
static __device__ __forceinline__ void cp16(u32 s, const void* g) {
    asm volatile("cp.async.cg.shared.global [%0],[%1],16;" :: "r"(s), "l"(g));
}
static __device__ __forceinline__ void cpcommit() {
    asm volatile("cp.async.commit_group;");
}

__global__ __launch_bounds__(320, 2)
void corr1d_hmma4(const float* __restrict__ x1, const float* __restrict__ x2,
                  float* __restrict__ out) {
    extern __shared__ __align__(16) char sm[];
    const int tid = threadIdx.x, wid = tid >> 5, lid = tid & 31;
    const int g = lid >> 2, tg = lid & 3;
    const int wt = blockIdx.x, h = blockIdx.y, b = blockIdx.z;
    const int W0 = wt * 160;
    const u32 sbase = (u32)__cvta_generic_to_shared(sm);

    const float* X1 = x1 + ((size_t)b * Cc) * CHW + (size_t)h * Ww;
    const float* X2 = x2 + ((size_t)b * Cc) * CHW + (size_t)h * Ww;

    // ---- cp.async tasks ----
    // A: 640 chunks (c 0..15, wq 0..39), 2/thread; staging pitch 656B
    const float* gsA[2]; u32 raA[2];
#pragma unroll
    for (int t = 0; t < 2; t++) {
        int idx = tid + 320 * t, c = idx / 40, wq = idx % 40;
        gsA[t] = X1 + (size_t)c * CHW + W0 + 4 * wq;
        raA[t] = (u32)(c * 656 + wq * 16);
    }
    // B: 800 chunks (c 0..15, q 0..49), w = W0-20+4q
    const float* gsB[3]; u32 raB[3]; bool okB[3];
#pragma unroll
    for (int t = 0; t < 3; t++) {
        int idx = tid + 320 * t, c = (idx / 50 < 16) ? idx / 50 : 15, q = idx % 50;
        int w = W0 - 20 + 4 * q;
        okB[t] = (idx < 800) && (w >= 0) && (w + 3 < Ww);
        gsB[t] = X2 + (size_t)c * CHW + (okB[t] ? w : 0);
        raB[t] = (u32)(c * 800 + q * 16);
    }
    // pre-zero static OOB B staging chunks (5 per c-row per slot)
    if (tid < 160) {
        int slot = tid / 80, rem = tid % 80, r = rem / 5;
        int qz = rem % 5 + (wt ? 45 : 0);
        *(uint4*)(sm + STG_B + slot * SLOT_B + r * 800 + qz * 16) =
            make_uint4(0, 0, 0, 0);
    }

    // ---- B fill read-back tasks ----
    const int jB0 = (tid < 200) ? tid : tid - 200;
    const int hB0 = (tid < 200) ? 0 : 1;
    const int jB1 = tid + 120;
    const bool vB1 = (tid < 80);
    const u32 stB0 = swz16(2 * jB0 + hB0);
    const u32 stB1 = swz16(2 * jB1 + 1);

    // ---- fragment lane offsets (B planes) ----
    const int m0 = wid * 16;
    const u32 offB = swz16(2 * (m0 + (lid & 7) + 8 * (lid >> 4)) + ((lid >> 3) & 1));
    int n6 = m0 + 48 + (lid & 7) + 8 * (lid >> 4);
    if (n6 > 199) n6 = 199;
    const u32 offB6 = swz16(2 * n6 + ((lid >> 3) & 1));

    float acc[7][4];
#pragma unroll
    for (int nt = 0; nt < 7; nt++)
#pragma unroll
        for (int i = 0; i < 4; i++) acc[nt][i] = 0.0f;

    // prologue: chunk 0 -> slot 0
#pragma unroll
    for (int t = 0; t < 2; t++) cp16(sbase + raA[t], gsA[t]);
#pragma unroll
    for (int t = 0; t < 3; t++) if (okB[t]) cp16(sbase + STG_B + raB[t], gsB[t]);
    cpcommit();

#pragma unroll 1
    for (int kk = 0; kk < NCH; kk++) {
        const int slot = kk & 1;
        if (kk + 1 < NCH) {
            const u32 baseA = sbase + (u32)((slot ^ 1) * SLOT_A);
            const u32 baseB = sbase + STG_B + (u32)((slot ^ 1) * SLOT_B);
#pragma unroll
            for (int t = 0; t < 2; t++) {
                gsA[t] += (size_t)16 * CHW;
                cp16(baseA + raA[t], gsA[t]);
            }
#pragma unroll
            for (int t = 0; t < 3; t++) {
                gsB[t] += (size_t)16 * CHW;
                if (okB[t]) cp16(baseB + raB[t], gsB[t]);
            }
            cpcommit();
            asm volatile("cp.async.wait_group 1;");
        } else {
            asm volatile("cp.async.wait_group 0;");
        }
        __syncthreads();   // staging kk visible

        // fill: B staging -> split -> bf16 planes (B only)
        char* bufc = sm + BPL + slot * PLB;
        const float* sgB = (const float*)(sm + STG_B + slot * SLOT_B);
        {
            float v[8]; u32 h0, h1, h2, h3, l0, l1, l2, l3;
#pragma unroll
            for (int e = 0; e < 8; e++) v[e] = sgB[(hB0 * 8 + e) * 200 + jB0];
            fsplit(v[0], v[1], h0, l0); fsplit(v[2], v[3], h1, l1);
            fsplit(v[4], v[5], h2, l2); fsplit(v[6], v[7], h3, l3);
            *(uint4*)(bufc + stB0) = make_uint4(h0, h1, h2, h3);
            *(uint4*)(bufc + B_LO + stB0) = make_uint4(l0, l1, l2, l3);
            if (vB1) {
#pragma unroll
                for (int e = 0; e < 8; e++) v[e] = sgB[(8 + e) * 200 + jB1];
                fsplit(v[0], v[1], h0, l0); fsplit(v[2], v[3], h1, l1);
                fsplit(v[4], v[5], h2, l2); fsplit(v[6], v[7], h3, l3);
                *(uint4*)(bufc + stB1) = make_uint4(h0, h1, h2, h3);
                *(uint4*)(bufc + B_LO + stB1) = make_uint4(l0, l1, l2, l3);
            }
        }

        // A fragments: direct fp32 loads from staging (conflict-free), split in regs
        u32 ah[4], al[4];
        {
            const float* sgA = (const float*)(sm + slot * SLOT_A);
            const float* pa = sgA + m0 + g;
            float v0 = pa[(2 * tg) * PA],     v1 = pa[(2 * tg + 1) * PA];
            float v2 = pa[(2 * tg + 8) * PA], v3 = pa[(2 * tg + 9) * PA];
            fsplit(v0, v1, ah[0], al[0]);
            fsplit(v2, v3, ah[2], al[2]);
            const float* pb = pa + 8;
            v0 = pb[(2 * tg) * PA];     v1 = pb[(2 * tg + 1) * PA];
            v2 = pb[(2 * tg + 8) * PA]; v3 = pb[(2 * tg + 9) * PA];
            fsplit(v0, v1, ah[1], al[1]);
            fsplit(v2, v3, ah[3], al[3]);
        }
        __syncthreads();   // B planes ready

        // B fragments + mma
        const u32 bufs = sbase + BPL + (u32)(slot * PLB);
#pragma unroll
        for (int p = 0; p < 3; p++) {
            u32 bh[4], bl[4];
            ldsm4(bh, bufs + offB + 512u * p);
            ldsm4(bl, bufs + B_LO + offB + 512u * p);
            mma16816(acc[2 * p], ah, bh);
            mma16816(acc[2 * p + 1], ah, bh + 2);
            mma16816(acc[2 * p], al, bh);
            mma16816(acc[2 * p + 1], al, bh + 2);
            mma16816(acc[2 * p], ah, bl);
            mma16816(acc[2 * p + 1], ah, bl + 2);
        }
        u32 b6h[2], b6l[2];
        ldsm2(b6h, bufs + offB6);
        ldsm2(b6l, bufs + B_LO + offB6);
        mma16816(acc[6], ah, b6h);
        mma16816(acc[6], al, b6h);
        mma16816(acc[6], ah, b6l);
    }

    __syncthreads();

    // ---- band stage: band[m][d] = D[m][j], d = j - m (m local) ----
    float* band = (float*)sm;
#pragma unroll
    for (int nt = 0; nt < 7; nt++) {
        int jl = 8 * nt + 2 * tg;
        int d0 = jl - g, d2 = jl - g - 8;
        if (d0 >= 0 && d0 < Dd) band[(m0 + g) * BP + d0] = acc[nt][0];
        if (d0 + 1 >= 0 && d0 + 1 < Dd) band[(m0 + g) * BP + d0 + 1] = acc[nt][1];
        if (d2 >= 0 && d2 < Dd) band[(m0 + g + 8) * BP + d2] = acc[nt][2];
        if (d2 + 1 >= 0 && d2 + 1 < Dd) band[(m0 + g + 8) * BP + d2 + 1] = acc[nt][3];
    }
    __syncthreads();

    const int w = tid % 160;
    float* ob = out + ((size_t)b * Dd * Hh + h) * Ww + W0 + w;
#pragma unroll 1
    for (int d = tid / 160; d < Dd; d += 2)
        ob[(size_t)d * Hh * Ww] = band[w * BP + d];
}

extern "C" void kernel_launch(void* const* d_in, const int* in_sizes, int n_in,
                              void* d_out, int out_size) {
    const float* x1 = (const float*)d_in[0];
    const float* x2 = (const float*)d_in[1];
    float* out = (float*)d_out;
    cudaFuncSetAttribute(corr1d_hmma4,
                         cudaFuncAttributeMaxDynamicSharedMemorySize, SMEMB);
    dim3 grid(2, Hh, 8);
    corr1d_hmma4<<<grid, 320, SMEMB>>>(x1, x2, out);
}